// round 13
// baseline (speedup 1.0000x reference)
#include <cuda_runtime.h>
#include <cuda_fp16.h>
#include <cstdint>
#include <cstddef>

// ---------------------------------------------------------------------------
// DecayBlock (Mamba-2 SSD block) — round 13: branched-graph overlap.
//   GEMMs are at the legacy-mma path ceiling (~50% tensor counter, R6-R9
//   asymptote). Remaining win = overlap the SSD tail with the GEMMs:
//   split the pipeline by batch halves onto 2 streams (graph-captured DAG),
//   and fold the weight fp32->fp16 conversion into wgemm.
// ---------------------------------------------------------------------------

namespace {
constexpr int B_  = 8;
constexpr int S_  = 4096;
constexpr int DM_ = 1024;
constexpr int H_  = 16;
constexpr int N_  = 64;
constexpr int C_  = 64;
constexpr int M_  = B_ * S_;
constexpr int SHH = 72;
constexpr int A_STAGE = 128 * SHH * 2;
constexpr int B_STAGE = 256 * SHH * 2;
constexpr int NSTAGE  = 3;
constexpr int GEMM_SMEM = NSTAGE * (A_STAGE + B_STAGE);   // 165888 B

constexpr int WSTR = 1028;
constexpr int XSTR = 68;
constexpr int WGEMM_SMEM = (16 * WSTR + 256 * XSTR) * 4;  // 135424 B

constexpr int TROWS = 259;
constexpr int TPAD  = 72;
}

// Scratch (allocation-free: __device__ globals)
__device__ __align__(16) __half g_xih[(size_t)M_ * DM_];
__device__ __align__(16) float  g_wc[(size_t)M_ * H_];
__device__ __align__(16) __half g_xh[(size_t)M_ * DM_];
__device__ __align__(16) __half g_yh[(size_t)M_ * DM_];
__device__ __align__(16) __half g_ipwh[(size_t)DM_ * DM_];
__device__ __align__(16) __half g_opwh[(size_t)DM_ * DM_];
__device__ __align__(16) float g_states[B_ * H_ * C_ * N_];
__device__ float g_cnorm[B_ * H_ * C_];
__device__ float g_T[B_ * H_ * C_];
__device__ __align__(16) float g_nstates[B_ * H_ * C_ * N_];
__device__ float g_nnorm[B_ * H_ * C_];

__device__ __forceinline__ uint32_t pk(float lo, float hi) {
    __half2 h = __floats2half2_rn(lo, hi);
    return *reinterpret_cast<uint32_t*>(&h);
}

__device__ __forceinline__ void mma_f16(float* c, const uint32_t* a, const uint32_t* b) {
    asm volatile(
        "mma.sync.aligned.m16n8k16.row.col.f32.f16.f16.f32 "
        "{%0,%1,%2,%3}, {%4,%5,%6,%7}, {%8,%9}, {%0,%1,%2,%3};\n"
        : "+f"(c[0]), "+f"(c[1]), "+f"(c[2]), "+f"(c[3])
        : "r"(a[0]), "r"(a[1]), "r"(a[2]), "r"(a[3]), "r"(b[0]), "r"(b[1]));
}

__device__ __forceinline__ void cp16(uint32_t smem, const void* gmem) {
    asm volatile("cp.async.cg.shared.global [%0], [%1], 16;\n" :: "r"(smem), "l"(gmem));
}

__device__ __forceinline__ void ldsm4(uint32_t* r, uint32_t addr) {
    asm volatile("ldmatrix.sync.aligned.m8n8.x4.shared.b16 {%0,%1,%2,%3}, [%4];"
                 : "=r"(r[0]), "=r"(r[1]), "=r"(r[2]), "=r"(r[3]) : "r"(addr));
}

__device__ __forceinline__ void stage_tile(__half (*sx)[TPAD], int b, int s_tile0,
                                           int h, int tid)
{
#pragma unroll
    for (int j = 0; j < 9; j++) {
        const int idx = tid + j * 256;
        if (idx < TROWS * 8) {
            const int row = idx >> 3;
            const int q   = idx & 7;
            const int s   = s_tile0 + row;
            uint4 v = make_uint4(0, 0, 0, 0);
            if (s >= 0)
                v = *reinterpret_cast<const uint4*>(
                    g_xih + (size_t)(b * S_ + s) * DM_ + h * 64 + q * 8);
            *reinterpret_cast<uint4*>(&sx[row][q * 8]) = v;
        }
    }
}

// ---------------------------------------------------------------------------
// FP16 tensor GEMM (NT), m_base for half-pipeline splits.
// ---------------------------------------------------------------------------
template <bool FIRST>
__global__ __launch_bounds__(512)
void hgemm_tc(float* __restrict__ Carg, int K, int m_base)
{
    const __half* A  = FIRST ? g_xh   : g_yh;
    const __half* Bw = FIRST ? g_ipwh : g_opwh;

    extern __shared__ __align__(16) char smem[];
    const uint32_t sbase = (uint32_t)__cvta_generic_to_shared(smem);

    const int tid  = threadIdx.x;
    const int lane = tid & 31;
    const int warp = tid >> 5;
    const int wm   = warp & 3;
    const int wn   = warp >> 2;
    const int grp  = lane >> 2;
    const int tig  = lane & 3;

    const int m0 = m_base + blockIdx.y * 128;
    const int n0 = blockIdx.x * 256;

    const int srow = tid >> 2;
    const int sc16 = (tid & 3) * 16;

    const __half* gA  = A  + (size_t)(m0 + srow) * K + sc16;
    const __half* gB0 = Bw + (size_t)(n0 + srow) * K + sc16;
    const __half* gB1 = Bw + (size_t)(n0 + 128 + srow) * K + sc16;

    const uint32_t dAoff  = (uint32_t)(srow * SHH + sc16) * 2;
    const uint32_t dB0off = dAoff;
    const uint32_t dB1off = (uint32_t)((srow + 128) * SHH + sc16) * 2;

    const uint32_t laneA = ((lane & 15) * SHH + (lane >> 4) * 8) * 2;
    const uint32_t laneB = (((lane & 7) + ((lane >> 4) << 3)) * SHH +
                            ((lane >> 3) & 1) * 8) * 2;

    float acc[2][8][4];
#pragma unroll
    for (int i = 0; i < 2; i++)
#pragma unroll
        for (int j = 0; j < 8; j++)
#pragma unroll
            for (int r = 0; r < 4; r++) acc[i][j][r] = 0.f;

    auto aBase = [&](int st) { return sbase + st * A_STAGE; };
    auto bBase = [&](int st) { return sbase + NSTAGE * A_STAGE + st * B_STAGE; };

    auto load_stage = [&](int st, int k0) {
        cp16(aBase(st) + dAoff,       gA  + k0);
        cp16(aBase(st) + dAoff + 16,  gA  + k0 + 8);
        cp16(bBase(st) + dB0off,      gB0 + k0);
        cp16(bBase(st) + dB0off + 16, gB0 + k0 + 8);
        cp16(bBase(st) + dB1off,      gB1 + k0);
        cp16(bBase(st) + dB1off + 16, gB1 + k0 + 8);
    };

    const int NIT = K >> 6;
    load_stage(0, 0);
    asm volatile("cp.async.commit_group;\n" ::: "memory");
    load_stage(1, 64);
    asm volatile("cp.async.commit_group;\n" ::: "memory");

    for (int it = 0; it < NIT; ++it) {
        const int cur = it % NSTAGE;
        if (it < NIT - 1) {
            asm volatile("cp.async.wait_group 1;\n" ::: "memory");
        } else {
            asm volatile("cp.async.wait_group 0;\n" ::: "memory");
        }
        __syncthreads();

        if (it + 2 < NIT) {
            load_stage((it + 2) % NSTAGE, (it + 2) << 6);
            asm volatile("cp.async.commit_group;\n" ::: "memory");
        }

        const uint32_t aSt = aBase(cur);
        const uint32_t bSt = bBase(cur);

        uint32_t afr[2][2][4], bfr[2][4][4];
        auto ldfrag = [&](int buf, int ks) {
#pragma unroll
            for (int mt = 0; mt < 2; mt++)
                ldsm4(afr[buf][mt],
                      aSt + (wm * 32 + mt * 16) * (SHH * 2) + ks * 32 + laneA);
#pragma unroll
            for (int np = 0; np < 4; np++)
                ldsm4(bfr[buf][np],
                      bSt + (wn * 64 + np * 16) * (SHH * 2) + ks * 32 + laneB);
        };
        ldfrag(0, 0);
#pragma unroll
        for (int ks = 0; ks < 4; ks++) {
            const int cb = ks & 1;
            if (ks < 3) ldfrag(cb ^ 1, ks + 1);
#pragma unroll
            for (int mt = 0; mt < 2; mt++)
#pragma unroll
                for (int nt = 0; nt < 8; nt++)
                    mma_f16(acc[mt][nt], afr[cb][mt], &bfr[cb][nt >> 1][(nt & 1) * 2]);
        }
    }
    __syncthreads();

#pragma unroll
    for (int mt = 0; mt < 2; mt++) {
        const int row = m0 + wm * 32 + mt * 16 + grp;
#pragma unroll
        for (int nt = 0; nt < 8; nt++) {
            const int col = n0 + wn * 64 + nt * 8 + tig * 2;
            if (FIRST) {
                *reinterpret_cast<uint32_t*>(
                    &g_xih[(size_t)row * DM_ + col]) = pk(acc[mt][nt][0], acc[mt][nt][1]);
                *reinterpret_cast<uint32_t*>(
                    &g_xih[(size_t)(row + 8) * DM_ + col]) = pk(acc[mt][nt][2], acc[mt][nt][3]);
            } else {
                *reinterpret_cast<float2*>(&Carg[(size_t)row * DM_ + col]) =
                    make_float2(acc[mt][nt][0], acc[mt][nt][1]);
                *reinterpret_cast<float2*>(&Carg[(size_t)(row + 8) * DM_ + col]) =
                    make_float2(acc[mt][nt][2], acc[mt][nt][3]);
            }
        }
    }
}

// ---------------------------------------------------------------------------
// K1b: w-cols fp32 GEMM + x fp16 emit + BOTH weight fp16 conversions.
// ---------------------------------------------------------------------------
__global__ __launch_bounds__(512)
void wgemm_kernel(const float* __restrict__ x, const float* __restrict__ ipw,
                  const float* __restrict__ opw)
{
    extern __shared__ __align__(16) float fsm[];
    float* Ws = fsm;                 // [16][WSTR]
    float* Xs = fsm + 16 * WSTR;     // [256][XSTR]

    const int tid = threadIdx.x;
    const int cq4 = (tid & 3) * 4;
    const int rg  = tid >> 2;
    const int m0  = blockIdx.x * 256;
    const int gtid = blockIdx.x * 512 + tid;   // 0..65535

    // fused weight conversions: 262144 float4 per matrix / 65536 thr = 4 each
    {
        const float4* i4 = reinterpret_cast<const float4*>(ipw);
        const float4* o4 = reinterpret_cast<const float4*>(opw);
#pragma unroll
        for (int j = 0; j < 4; j++) {
            const int i = gtid + j * 65536;
            float4 v = i4[i];
            reinterpret_cast<uint2*>(g_ipwh)[i] = make_uint2(pk(v.x, v.y), pk(v.z, v.w));
            float4 w = o4[i];
            reinterpret_cast<uint2*>(g_opwh)[i] = make_uint2(pk(w.x, w.y), pk(w.z, w.w));
        }
    }

    const float4* wsrc = reinterpret_cast<const float4*>(ipw + (size_t)1024 * DM_);
#pragma unroll
    for (int j = 0; j < 8; j++) {
        const int w4 = j * 512 + tid;
        float4 v = wsrc[w4];
        const int r  = w4 >> 8;
        const int cw = (w4 & 255) * 4;
        *reinterpret_cast<float4*>(Ws + r * WSTR + cw) = v;
    }

    float acc[2][4];
#pragma unroll
    for (int r = 0; r < 2; r++)
#pragma unroll
        for (int c = 0; c < 4; c++) acc[r][c] = 0.f;

    const int lrow = tid >> 1;
    const int lk0  = (tid & 1) * 32;

    for (int kc = 0; kc < 16; kc++) {
        const int k0 = kc * 64;
        {
            const float* xsrc = x + (size_t)(m0 + lrow) * DM_ + k0 + lk0;
            __half* xhd = g_xh + (size_t)(m0 + lrow) * DM_ + k0 + lk0;
            float* xdst = Xs + lrow * XSTR + lk0;
#pragma unroll
            for (int q = 0; q < 8; q++) {
                float4 v = *reinterpret_cast<const float4*>(xsrc + q * 4);
                *reinterpret_cast<float4*>(xdst + q * 4) = v;
                *reinterpret_cast<uint2*>(xhd + q * 4) =
                    make_uint2(pk(v.x, v.y), pk(v.z, v.w));
            }
        }
        __syncthreads();

#pragma unroll 4
        for (int k4 = 0; k4 < 16; k4++) {
            float4 xv0 = *reinterpret_cast<const float4*>(Xs + rg * XSTR + k4 * 4);
            float4 xv1 = *reinterpret_cast<const float4*>(Xs + (rg + 128) * XSTR + k4 * 4);
#pragma unroll
            for (int cc = 0; cc < 4; cc++) {
                float4 wv = *reinterpret_cast<const float4*>(
                    Ws + (cq4 + cc) * WSTR + k0 + k4 * 4);
                acc[0][cc] = fmaf(xv0.x, wv.x, acc[0][cc]);
                acc[0][cc] = fmaf(xv0.y, wv.y, acc[0][cc]);
                acc[0][cc] = fmaf(xv0.z, wv.z, acc[0][cc]);
                acc[0][cc] = fmaf(xv0.w, wv.w, acc[0][cc]);
                acc[1][cc] = fmaf(xv1.x, wv.x, acc[1][cc]);
                acc[1][cc] = fmaf(xv1.y, wv.y, acc[1][cc]);
                acc[1][cc] = fmaf(xv1.z, wv.z, acc[1][cc]);
                acc[1][cc] = fmaf(xv1.w, wv.w, acc[1][cc]);
            }
        }
        __syncthreads();
    }

#pragma unroll
    for (int r = 0; r < 2; r++) {
        const int row = m0 + rg + r * 128;
        *reinterpret_cast<float4*>(&g_wc[(size_t)row * H_ + cq4]) =
            make_float4(acc[r][0], acc[r][1], acc[r][2], acc[r][3]);
    }
}

// ---------------------------------------------------------------------------
// K2: chunk stats (smem-staged), b_base for half split.
// ---------------------------------------------------------------------------
__global__ __launch_bounds__(256)
void chunk_stats_kernel(const float* __restrict__ conv_w,
                        const float* __restrict__ conv_b,
                        const float* __restrict__ w_base, int b_base)
{
    const int ty = threadIdx.y;
    const int c  = blockIdx.x * 4 + ty;
    const int h  = blockIdx.y;
    const int b  = b_base + blockIdx.z;
    const int n  = threadIdx.x;
    const int tid = ty * 64 + n;

    __shared__ __half sx[TROWS][TPAD];
    __shared__ float sS[4][64];
    __shared__ float sE[4][64];
    __shared__ float sMin[4];

    stage_tile(sx, b, blockIdx.x * 256 - 3, h, tid);

    const int ch = h * 64 + n;
    const float cw0 = conv_w[ch * 4 + 0];
    const float cw1 = conv_w[ch * 4 + 1];
    const float cw2 = conv_w[ch * 4 + 2];
    const float cw3 = conv_w[ch * 4 + 3];
    const float cb  = conv_b[ch];

    const int s0 = c * 64;
    sS[ty][n] = g_wc[(size_t)(b * S_ + s0 + n) * H_ + h] * w_base[h];
    __syncthreads();

    if (n == 0) {
        float run = 0.f, mn = 3.4e38f;
        for (int i = 0; i < 64; i++) {
            run += sS[ty][i];
            sS[ty][i] = run;
            mn = fminf(mn, run);
        }
        sMin[ty] = mn;
    }
    __syncthreads();
    sE[ty][n] = __expf(-sS[ty][n]);
    __syncthreads();

    const int r0 = ty * 64;
    float xm3 = __half2float(sx[r0 + 0][n]);
    float xm2 = __half2float(sx[r0 + 1][n]);
    float xm1 = __half2float(sx[r0 + 2][n]);

    float r = 0.f, rn = 0.f;
#pragma unroll 8
    for (int i = 0; i < 64; i++) {
        const float x0 = __half2float(sx[r0 + 3 + i][n]);
        const float xv = cb + cw0 * xm3 + cw1 * xm2 + cw2 * xm1 + cw3 * x0;
        xm3 = xm2; xm2 = xm1; xm1 = x0;
        const float e = sE[ty][i];
        r  = fmaf(e, xv, r);
        rn += e;
    }

    const float sc  = __expf(sMin[ty]);
    const int   idx = (b * H_ + h) * C_ + c;
    g_states[idx * N_ + n] = sc * r;
    if (n == 0) {
        g_cnorm[idx] = sc * rn;
        g_T[idx]     = sS[ty][63];
    }
}

// ---------------------------------------------------------------------------
// K3: cross-chunk scan, b_base for half split.
// ---------------------------------------------------------------------------
__global__ __launch_bounds__(256)
void chunk_scan_kernel(int b_base)
{
    const int h = blockIdx.x;
    const int b = b_base + blockIdx.y;
    const int tid = threadIdx.x;
    const int n  = tid & 63;
    const int zq = tid >> 6;

    __shared__ float G[65];
    __shared__ float MP[64];
    __shared__ float W[64][64];
    __shared__ float st[64][64];
    __shared__ float cn[64];

    const int base = (b * H_ + h) * C_;

    for (int idx = tid; idx < 4096; idx += 256)
        st[idx >> 6][idx & 63] = g_states[(size_t)base * N_ + idx];
    if (tid < 64) cn[tid] = g_cnorm[base + tid];
    __syncthreads();

    if (tid == 0) {
        float run = 0.f;
        G[0] = 0.f;
        for (int c = 0; c < 64; c++) { run += g_T[base + c]; G[c + 1] = run; }
        float mn = 3.4e38f;
        for (int z = 0; z < 64; z++) { mn = fminf(mn, G[z]); MP[z] = mn; }
    }
    __syncthreads();

    for (int idx = tid; idx < 4096; idx += 256) {
        const int z = idx >> 6, cp = idx & 63;
        W[z][cp] = (cp < z) ? __expf(MP[z] - G[cp + 1]) : 0.f;
    }
    __syncthreads();

    for (int z = zq; z < 64; z += 4) {
        float accv = 0.f;
        for (int cp = 0; cp < z; cp++) accv = fmaf(W[z][cp], st[cp][n], accv);
        g_nstates[(base + z) * N_ + n] = accv;
    }
    if (tid < 64) {
        float accn = 0.f;
        for (int cp = 0; cp < tid; cp++) accn = fmaf(W[tid][cp], cn[cp], accn);
        g_nnorm[base + tid] = accn;
    }
}

// ---------------------------------------------------------------------------
// K4: combine -> y fp16 (smem-staged), b_base for half split.
// ---------------------------------------------------------------------------
__global__ __launch_bounds__(256)
void combine_kernel(const float* __restrict__ conv_w,
                    const float* __restrict__ conv_b,
                    const float* __restrict__ w_base, int b_base)
{
    const int ty = threadIdx.y;
    const int c  = blockIdx.x * 4 + ty;
    const int h  = blockIdx.y;
    const int b  = b_base + blockIdx.z;
    const int n  = threadIdx.x;
    const int tid = ty * 64 + n;

    __shared__ __half sx[TROWS][TPAD];
    __shared__ float sS[4][64];
    __shared__ float sE[4][64], sEMP[4][64], sSDO[4][64];
    __shared__ float sMP[4][64];
    __shared__ float sMax[4];

    stage_tile(sx, b, blockIdx.x * 256 - 3, h, tid);

    const int ch = h * 64 + n;
    const float cw0 = conv_w[ch * 4 + 0];
    const float cw1 = conv_w[ch * 4 + 1];
    const float cw2 = conv_w[ch * 4 + 2];
    const float cw3 = conv_w[ch * 4 + 3];
    const float cb  = conv_b[ch];

    const int s0 = c * 64;
    sS[ty][n] = g_wc[(size_t)(b * S_ + s0 + n) * H_ + h] * w_base[h];
    __syncthreads();

    if (n == 0) {
        float run = 0.f, mn = 3.4e38f, mx = -3.4e38f;
        for (int i = 0; i < 64; i++) {
            run += sS[ty][i];
            sS[ty][i] = run;
            mn = fminf(mn, run);
            sMP[ty][i] = mn;
            mx = fmaxf(mx, run);
        }
        sMax[ty] = mx;
    }
    __syncthreads();
    sE[ty][n]   = __expf(-sS[ty][n]);
    sEMP[ty][n] = __expf(sMP[ty][n]);
    sSDO[ty][n] = __expf(sS[ty][n] - sMax[ty]);
    __syncthreads();

    const int idx = (b * H_ + h) * C_ + c;
    const float ns = g_nstates[idx * N_ + n];
    const float nn = g_nnorm[idx];

    const int r0 = ty * 64;
    float xm3 = __half2float(sx[r0 + 0][n]);
    float xm2 = __half2float(sx[r0 + 1][n]);
    float xm1 = __half2float(sx[r0 + 2][n]);

    float r = 0.f, rn = 0.f;
    __half* yout = g_yh + (size_t)(b * S_ + s0) * DM_ + h * 64 + n;

#pragma unroll 8
    for (int i = 0; i < 64; i++) {
        const float x0 = __half2float(sx[r0 + 3 + i][n]);
        const float xv = cb + cw0 * xm3 + cw1 * xm2 + cw2 * xm1 + cw3 * x0;
        xm3 = xm2; xm2 = xm1; xm1 = x0;
        const float e = sE[ty][i];
        r  = fmaf(e, xv, r);
        rn += e;
        const float emp = sEMP[ty][i];
        const float sdo = sSDO[ty][i];
        const float num = fmaf(sdo, ns, emp * r);
        const float den = fmaf(sdo, nn, emp * rn);
        yout[(size_t)i * DM_] = __float2half_rn(num / den);
    }
}

// ---------------------------------------------------------------------------
// Launch: branched graph over 2 streams (split by batch halves).
// ---------------------------------------------------------------------------
extern "C" void kernel_launch(void* const* d_in, const int* in_sizes, int n_in,
                              void* d_out, int out_size)
{
    const float *x = nullptr, *ipw = nullptr, *cw = nullptr,
                *cb = nullptr, *wb = nullptr, *opw = nullptr;
    for (int i = 0; i < n_in; i++) {
        switch (in_sizes[i]) {
            case M_ * DM_:         x   = (const float*)d_in[i]; break;
            case (DM_ + H_) * DM_: ipw = (const float*)d_in[i]; break;
            case DM_ * 4:          cw  = (const float*)d_in[i]; break;
            case DM_:              cb  = (const float*)d_in[i]; break;
            case H_:               wb  = (const float*)d_in[i]; break;
            case DM_ * DM_:        opw = (const float*)d_in[i]; break;
        }
    }

    static cudaStream_t s1 = nullptr;
    static cudaEvent_t e1 = nullptr, e2 = nullptr;
    if (!s1) {
        cudaFuncSetAttribute(hgemm_tc<true>,
                             cudaFuncAttributeMaxDynamicSharedMemorySize, GEMM_SMEM);
        cudaFuncSetAttribute(hgemm_tc<false>,
                             cudaFuncAttributeMaxDynamicSharedMemorySize, GEMM_SMEM);
        cudaFuncSetAttribute(wgemm_kernel,
                             cudaFuncAttributeMaxDynamicSharedMemorySize, WGEMM_SMEM);
        cudaStreamCreateWithFlags(&s1, cudaStreamNonBlocking);
        cudaEventCreateWithFlags(&e1, cudaEventDisableTiming);
        cudaEventCreateWithFlags(&e2, cudaEventDisableTiming);
    }

    float* out = (float*)d_out;
    const dim3 gHalf(DM_ / 256, M_ / 256);      // 4 x 128 (half of M)
    const dim3 gStats(C_ / 4, H_, B_ / 2);      // 16 x 16 x 4
    const dim3 bStats(64, 4);
    const dim3 gScan(H_, B_ / 2);

    // K1b: wgemm (+x fp16, +both weight fp16) — whole M
    wgemm_kernel<<<M_ / 256, 512, WGEMM_SMEM>>>(x, ipw, opw);

    // hgemm1 first half (b0-3)
    hgemm_tc<true><<<gHalf, 512, GEMM_SMEM>>>(nullptr, DM_, 0);
    cudaEventRecord(e1, 0);

    // default stream continues: hgemm1 second half (b4-7)
    hgemm_tc<true><<<gHalf, 512, GEMM_SMEM>>>(nullptr, DM_, M_ / 2);

    // stream 1: first-half SSD tail + hgemm2(b0-3), overlapped with above
    cudaStreamWaitEvent(s1, e1, 0);
    chunk_stats_kernel<<<gStats, bStats, 0, s1>>>(cw, cb, wb, 0);
    chunk_scan_kernel<<<gScan, 256, 0, s1>>>(0);
    combine_kernel<<<gStats, bStats, 0, s1>>>(cw, cb, wb, 0);
    hgemm_tc<false><<<gHalf, 512, GEMM_SMEM, s1>>>(out, DM_, 0);
    cudaEventRecord(e2, s1);

    // default stream: second-half SSD tail + hgemm2(b4-7)
    chunk_stats_kernel<<<gStats, bStats>>>(cw, cb, wb, B_ / 2);
    chunk_scan_kernel<<<gScan, 256>>>(B_ / 2);
    combine_kernel<<<gStats, bStats>>>(cw, cb, wb, B_ / 2);
    hgemm_tc<false><<<gHalf, 512, GEMM_SMEM>>>(out, DM_, M_ / 2);

    // join
    cudaStreamWaitEvent(0, e2, 0);
}

// round 14
// speedup vs baseline: 1.0473x; 1.0473x over previous
#include <cuda_runtime.h>
#include <cuda_fp16.h>
#include <cstdint>
#include <cstddef>

// ---------------------------------------------------------------------------
// DecayBlock (Mamba-2 SSD block) — round 14: revert R13 stream split (net
// regression: GEMM halves both saturate the chip; overlap bought nothing,
// wave quantization + launch edges cost 32us). Keep R12 linear pipeline,
// keep the one good R13 piece: weight f2h fused into wgemm.
// ---------------------------------------------------------------------------

namespace {
constexpr int B_  = 8;
constexpr int S_  = 4096;
constexpr int DM_ = 1024;
constexpr int H_  = 16;
constexpr int N_  = 64;
constexpr int C_  = 64;
constexpr int M_  = B_ * S_;
constexpr int SHH = 72;
constexpr int A_STAGE = 128 * SHH * 2;
constexpr int B_STAGE = 256 * SHH * 2;
constexpr int NSTAGE  = 3;
constexpr int GEMM_SMEM = NSTAGE * (A_STAGE + B_STAGE);   // 165888 B

constexpr int WSTR = 1028;
constexpr int XSTR = 68;
constexpr int WGEMM_SMEM = (16 * WSTR + 256 * XSTR) * 4;  // 135424 B

constexpr int TROWS = 259;
constexpr int TPAD  = 72;
}

// Scratch (allocation-free: __device__ globals)
__device__ __align__(16) __half g_xih[(size_t)M_ * DM_];
__device__ __align__(16) float  g_wc[(size_t)M_ * H_];
__device__ __align__(16) __half g_xh[(size_t)M_ * DM_];
__device__ __align__(16) __half g_yh[(size_t)M_ * DM_];
__device__ __align__(16) __half g_ipwh[(size_t)DM_ * DM_];
__device__ __align__(16) __half g_opwh[(size_t)DM_ * DM_];
__device__ __align__(16) float g_states[B_ * H_ * C_ * N_];
__device__ float g_cnorm[B_ * H_ * C_];
__device__ float g_T[B_ * H_ * C_];
__device__ __align__(16) float g_nstates[B_ * H_ * C_ * N_];
__device__ float g_nnorm[B_ * H_ * C_];

__device__ __forceinline__ uint32_t pk(float lo, float hi) {
    __half2 h = __floats2half2_rn(lo, hi);
    return *reinterpret_cast<uint32_t*>(&h);
}

__device__ __forceinline__ void mma_f16(float* c, const uint32_t* a, const uint32_t* b) {
    asm volatile(
        "mma.sync.aligned.m16n8k16.row.col.f32.f16.f16.f32 "
        "{%0,%1,%2,%3}, {%4,%5,%6,%7}, {%8,%9}, {%0,%1,%2,%3};\n"
        : "+f"(c[0]), "+f"(c[1]), "+f"(c[2]), "+f"(c[3])
        : "r"(a[0]), "r"(a[1]), "r"(a[2]), "r"(a[3]), "r"(b[0]), "r"(b[1]));
}

__device__ __forceinline__ void cp16(uint32_t smem, const void* gmem) {
    asm volatile("cp.async.cg.shared.global [%0], [%1], 16;\n" :: "r"(smem), "l"(gmem));
}

__device__ __forceinline__ void ldsm4(uint32_t* r, uint32_t addr) {
    asm volatile("ldmatrix.sync.aligned.m8n8.x4.shared.b16 {%0,%1,%2,%3}, [%4];"
                 : "=r"(r[0]), "=r"(r[1]), "=r"(r[2]), "=r"(r[3]) : "r"(addr));
}

__device__ __forceinline__ void stage_tile(__half (*sx)[TPAD], int b, int s_tile0,
                                           int h, int tid)
{
#pragma unroll
    for (int j = 0; j < 9; j++) {
        const int idx = tid + j * 256;
        if (idx < TROWS * 8) {
            const int row = idx >> 3;
            const int q   = idx & 7;
            const int s   = s_tile0 + row;
            uint4 v = make_uint4(0, 0, 0, 0);
            if (s >= 0)
                v = *reinterpret_cast<const uint4*>(
                    g_xih + (size_t)(b * S_ + s) * DM_ + h * 64 + q * 8);
            *reinterpret_cast<uint4*>(&sx[row][q * 8]) = v;
        }
    }
}

// ---------------------------------------------------------------------------
// FP16 tensor GEMM (NT): 128x256 block, 512 thr, warp tile 32x64, BK=64,
// 3-stage cp.async, ldmatrix double-buffer. FIRST -> fp16 out to g_xih.
// ---------------------------------------------------------------------------
template <bool FIRST>
__global__ __launch_bounds__(512)
void hgemm_tc(float* __restrict__ Carg, int K)
{
    const __half* A  = FIRST ? g_xh   : g_yh;
    const __half* Bw = FIRST ? g_ipwh : g_opwh;

    extern __shared__ __align__(16) char smem[];
    const uint32_t sbase = (uint32_t)__cvta_generic_to_shared(smem);

    const int tid  = threadIdx.x;
    const int lane = tid & 31;
    const int warp = tid >> 5;
    const int wm   = warp & 3;
    const int wn   = warp >> 2;
    const int grp  = lane >> 2;
    const int tig  = lane & 3;

    const int m0 = blockIdx.y * 128;
    const int n0 = blockIdx.x * 256;

    const int srow = tid >> 2;
    const int sc16 = (tid & 3) * 16;

    const __half* gA  = A  + (size_t)(m0 + srow) * K + sc16;
    const __half* gB0 = Bw + (size_t)(n0 + srow) * K + sc16;
    const __half* gB1 = Bw + (size_t)(n0 + 128 + srow) * K + sc16;

    const uint32_t dAoff  = (uint32_t)(srow * SHH + sc16) * 2;
    const uint32_t dB0off = dAoff;
    const uint32_t dB1off = (uint32_t)((srow + 128) * SHH + sc16) * 2;

    const uint32_t laneA = ((lane & 15) * SHH + (lane >> 4) * 8) * 2;
    const uint32_t laneB = (((lane & 7) + ((lane >> 4) << 3)) * SHH +
                            ((lane >> 3) & 1) * 8) * 2;

    float acc[2][8][4];
#pragma unroll
    for (int i = 0; i < 2; i++)
#pragma unroll
        for (int j = 0; j < 8; j++)
#pragma unroll
            for (int r = 0; r < 4; r++) acc[i][j][r] = 0.f;

    auto aBase = [&](int st) { return sbase + st * A_STAGE; };
    auto bBase = [&](int st) { return sbase + NSTAGE * A_STAGE + st * B_STAGE; };

    auto load_stage = [&](int st, int k0) {
        cp16(aBase(st) + dAoff,       gA  + k0);
        cp16(aBase(st) + dAoff + 16,  gA  + k0 + 8);
        cp16(bBase(st) + dB0off,      gB0 + k0);
        cp16(bBase(st) + dB0off + 16, gB0 + k0 + 8);
        cp16(bBase(st) + dB1off,      gB1 + k0);
        cp16(bBase(st) + dB1off + 16, gB1 + k0 + 8);
    };

    const int NIT = K >> 6;
    load_stage(0, 0);
    asm volatile("cp.async.commit_group;\n" ::: "memory");
    load_stage(1, 64);
    asm volatile("cp.async.commit_group;\n" ::: "memory");

    for (int it = 0; it < NIT; ++it) {
        const int cur = it % NSTAGE;
        if (it < NIT - 1) {
            asm volatile("cp.async.wait_group 1;\n" ::: "memory");
        } else {
            asm volatile("cp.async.wait_group 0;\n" ::: "memory");
        }
        __syncthreads();

        if (it + 2 < NIT) {
            load_stage((it + 2) % NSTAGE, (it + 2) << 6);
            asm volatile("cp.async.commit_group;\n" ::: "memory");
        }

        const uint32_t aSt = aBase(cur);
        const uint32_t bSt = bBase(cur);

        uint32_t afr[2][2][4], bfr[2][4][4];
        auto ldfrag = [&](int buf, int ks) {
#pragma unroll
            for (int mt = 0; mt < 2; mt++)
                ldsm4(afr[buf][mt],
                      aSt + (wm * 32 + mt * 16) * (SHH * 2) + ks * 32 + laneA);
#pragma unroll
            for (int np = 0; np < 4; np++)
                ldsm4(bfr[buf][np],
                      bSt + (wn * 64 + np * 16) * (SHH * 2) + ks * 32 + laneB);
        };
        ldfrag(0, 0);
#pragma unroll
        for (int ks = 0; ks < 4; ks++) {
            const int cb = ks & 1;
            if (ks < 3) ldfrag(cb ^ 1, ks + 1);
#pragma unroll
            for (int mt = 0; mt < 2; mt++)
#pragma unroll
                for (int nt = 0; nt < 8; nt++)
                    mma_f16(acc[mt][nt], afr[cb][mt], &bfr[cb][nt >> 1][(nt & 1) * 2]);
        }
    }
    __syncthreads();

#pragma unroll
    for (int mt = 0; mt < 2; mt++) {
        const int row = m0 + wm * 32 + mt * 16 + grp;
#pragma unroll
        for (int nt = 0; nt < 8; nt++) {
            const int col = n0 + wn * 64 + nt * 8 + tig * 2;
            if (FIRST) {
                *reinterpret_cast<uint32_t*>(
                    &g_xih[(size_t)row * DM_ + col]) = pk(acc[mt][nt][0], acc[mt][nt][1]);
                *reinterpret_cast<uint32_t*>(
                    &g_xih[(size_t)(row + 8) * DM_ + col]) = pk(acc[mt][nt][2], acc[mt][nt][3]);
            } else {
                *reinterpret_cast<float2*>(&Carg[(size_t)row * DM_ + col]) =
                    make_float2(acc[mt][nt][0], acc[mt][nt][1]);
                *reinterpret_cast<float2*>(&Carg[(size_t)(row + 8) * DM_ + col]) =
                    make_float2(acc[mt][nt][2], acc[mt][nt][3]);
            }
        }
    }
}

// ---------------------------------------------------------------------------
// K1b: w-cols fp32 GEMM + x fp16 emit + both weight fp16 conversions.
// ---------------------------------------------------------------------------
__global__ __launch_bounds__(512)
void wgemm_kernel(const float* __restrict__ x, const float* __restrict__ ipw,
                  const float* __restrict__ opw)
{
    extern __shared__ __align__(16) float fsm[];
    float* Ws = fsm;                 // [16][WSTR]
    float* Xs = fsm + 16 * WSTR;     // [256][XSTR]

    const int tid = threadIdx.x;
    const int cq4 = (tid & 3) * 4;
    const int rg  = tid >> 2;
    const int m0  = blockIdx.x * 256;
    const int gtid = blockIdx.x * 512 + tid;   // 0..65535

    // fused weight conversions: 262144 float4 per matrix / 65536 thr = 4 each
    {
        const float4* i4 = reinterpret_cast<const float4*>(ipw);
        const float4* o4 = reinterpret_cast<const float4*>(opw);
#pragma unroll
        for (int j = 0; j < 4; j++) {
            const int i = gtid + j * 65536;
            float4 v = i4[i];
            reinterpret_cast<uint2*>(g_ipwh)[i] = make_uint2(pk(v.x, v.y), pk(v.z, v.w));
            float4 w = o4[i];
            reinterpret_cast<uint2*>(g_opwh)[i] = make_uint2(pk(w.x, w.y), pk(w.z, w.w));
        }
    }

    const float4* wsrc = reinterpret_cast<const float4*>(ipw + (size_t)1024 * DM_);
#pragma unroll
    for (int j = 0; j < 8; j++) {
        const int w4 = j * 512 + tid;
        float4 v = wsrc[w4];
        const int r  = w4 >> 8;
        const int cw = (w4 & 255) * 4;
        *reinterpret_cast<float4*>(Ws + r * WSTR + cw) = v;
    }

    float acc[2][4];
#pragma unroll
    for (int r = 0; r < 2; r++)
#pragma unroll
        for (int c = 0; c < 4; c++) acc[r][c] = 0.f;

    const int lrow = tid >> 1;
    const int lk0  = (tid & 1) * 32;

    for (int kc = 0; kc < 16; kc++) {
        const int k0 = kc * 64;
        {
            const float* xsrc = x + (size_t)(m0 + lrow) * DM_ + k0 + lk0;
            __half* xhd = g_xh + (size_t)(m0 + lrow) * DM_ + k0 + lk0;
            float* xdst = Xs + lrow * XSTR + lk0;
#pragma unroll
            for (int q = 0; q < 8; q++) {
                float4 v = *reinterpret_cast<const float4*>(xsrc + q * 4);
                *reinterpret_cast<float4*>(xdst + q * 4) = v;
                *reinterpret_cast<uint2*>(xhd + q * 4) =
                    make_uint2(pk(v.x, v.y), pk(v.z, v.w));
            }
        }
        __syncthreads();

#pragma unroll 4
        for (int k4 = 0; k4 < 16; k4++) {
            float4 xv0 = *reinterpret_cast<const float4*>(Xs + rg * XSTR + k4 * 4);
            float4 xv1 = *reinterpret_cast<const float4*>(Xs + (rg + 128) * XSTR + k4 * 4);
#pragma unroll
            for (int cc = 0; cc < 4; cc++) {
                float4 wv = *reinterpret_cast<const float4*>(
                    Ws + (cq4 + cc) * WSTR + k0 + k4 * 4);
                acc[0][cc] = fmaf(xv0.x, wv.x, acc[0][cc]);
                acc[0][cc] = fmaf(xv0.y, wv.y, acc[0][cc]);
                acc[0][cc] = fmaf(xv0.z, wv.z, acc[0][cc]);
                acc[0][cc] = fmaf(xv0.w, wv.w, acc[0][cc]);
                acc[1][cc] = fmaf(xv1.x, wv.x, acc[1][cc]);
                acc[1][cc] = fmaf(xv1.y, wv.y, acc[1][cc]);
                acc[1][cc] = fmaf(xv1.z, wv.z, acc[1][cc]);
                acc[1][cc] = fmaf(xv1.w, wv.w, acc[1][cc]);
            }
        }
        __syncthreads();
    }

#pragma unroll
    for (int r = 0; r < 2; r++) {
        const int row = m0 + rg + r * 128;
        *reinterpret_cast<float4*>(&g_wc[(size_t)row * H_ + cq4]) =
            make_float4(acc[r][0], acc[r][1], acc[r][2], acc[r][3]);
    }
}

// ---------------------------------------------------------------------------
// K2: per-(b,h) 4-chunk stats — smem-staged tile.
// ---------------------------------------------------------------------------
__global__ __launch_bounds__(256)
void chunk_stats_kernel(const float* __restrict__ conv_w,
                        const float* __restrict__ conv_b,
                        const float* __restrict__ w_base)
{
    const int ty = threadIdx.y;
    const int c  = blockIdx.x * 4 + ty;
    const int h  = blockIdx.y, b = blockIdx.z;
    const int n  = threadIdx.x;
    const int tid = ty * 64 + n;

    __shared__ __half sx[TROWS][TPAD];
    __shared__ float sS[4][64];
    __shared__ float sE[4][64];
    __shared__ float sMin[4];

    stage_tile(sx, b, blockIdx.x * 256 - 3, h, tid);

    const int ch = h * 64 + n;
    const float cw0 = conv_w[ch * 4 + 0];
    const float cw1 = conv_w[ch * 4 + 1];
    const float cw2 = conv_w[ch * 4 + 2];
    const float cw3 = conv_w[ch * 4 + 3];
    const float cb  = conv_b[ch];

    const int s0 = c * 64;
    sS[ty][n] = g_wc[(size_t)(b * S_ + s0 + n) * H_ + h] * w_base[h];
    __syncthreads();

    if (n == 0) {
        float run = 0.f, mn = 3.4e38f;
        for (int i = 0; i < 64; i++) {
            run += sS[ty][i];
            sS[ty][i] = run;
            mn = fminf(mn, run);
        }
        sMin[ty] = mn;
    }
    __syncthreads();
    sE[ty][n] = __expf(-sS[ty][n]);
    __syncthreads();

    const int r0 = ty * 64;
    float xm3 = __half2float(sx[r0 + 0][n]);
    float xm2 = __half2float(sx[r0 + 1][n]);
    float xm1 = __half2float(sx[r0 + 2][n]);

    float r = 0.f, rn = 0.f;
#pragma unroll 8
    for (int i = 0; i < 64; i++) {
        const float x0 = __half2float(sx[r0 + 3 + i][n]);
        const float xv = cb + cw0 * xm3 + cw1 * xm2 + cw2 * xm1 + cw3 * x0;
        xm3 = xm2; xm2 = xm1; xm1 = x0;
        const float e = sE[ty][i];
        r  = fmaf(e, xv, r);
        rn += e;
    }

    const float sc  = __expf(sMin[ty]);
    const int   idx = (b * H_ + h) * C_ + c;
    g_states[idx * N_ + n] = sc * r;
    if (n == 0) {
        g_cnorm[idx] = sc * rn;
        g_T[idx]     = sS[ty][63];
    }
}

// ---------------------------------------------------------------------------
// K3: per-(b,h) cross-chunk scan — 256 threads.
// ---------------------------------------------------------------------------
__global__ __launch_bounds__(256)
void chunk_scan_kernel()
{
    const int h = blockIdx.x, b = blockIdx.y;
    const int tid = threadIdx.x;
    const int n  = tid & 63;
    const int zq = tid >> 6;

    __shared__ float G[65];
    __shared__ float MP[64];
    __shared__ float W[64][64];
    __shared__ float st[64][64];
    __shared__ float cn[64];

    const int base = (b * H_ + h) * C_;

    for (int idx = tid; idx < 4096; idx += 256)
        st[idx >> 6][idx & 63] = g_states[(size_t)base * N_ + idx];
    if (tid < 64) cn[tid] = g_cnorm[base + tid];
    __syncthreads();

    if (tid == 0) {
        float run = 0.f;
        G[0] = 0.f;
        for (int c = 0; c < 64; c++) { run += g_T[base + c]; G[c + 1] = run; }
        float mn = 3.4e38f;
        for (int z = 0; z < 64; z++) { mn = fminf(mn, G[z]); MP[z] = mn; }
    }
    __syncthreads();

    for (int idx = tid; idx < 4096; idx += 256) {
        const int z = idx >> 6, cp = idx & 63;
        W[z][cp] = (cp < z) ? __expf(MP[z] - G[cp + 1]) : 0.f;
    }
    __syncthreads();

    for (int z = zq; z < 64; z += 4) {
        float accv = 0.f;
        for (int cp = 0; cp < z; cp++) accv = fmaf(W[z][cp], st[cp][n], accv);
        g_nstates[(base + z) * N_ + n] = accv;
    }
    if (tid < 64) {
        float accn = 0.f;
        for (int cp = 0; cp < tid; cp++) accn = fmaf(W[tid][cp], cn[cp], accn);
        g_nnorm[base + tid] = accn;
    }
}

// ---------------------------------------------------------------------------
// K4: per-(b,h) 4-chunk combine -> y fp16 — smem-staged tile.
// ---------------------------------------------------------------------------
__global__ __launch_bounds__(256)
void combine_kernel(const float* __restrict__ conv_w,
                    const float* __restrict__ conv_b,
                    const float* __restrict__ w_base)
{
    const int ty = threadIdx.y;
    const int c  = blockIdx.x * 4 + ty;
    const int h  = blockIdx.y, b = blockIdx.z;
    const int n  = threadIdx.x;
    const int tid = ty * 64 + n;

    __shared__ __half sx[TROWS][TPAD];
    __shared__ float sS[4][64];
    __shared__ float sE[4][64], sEMP[4][64], sSDO[4][64];
    __shared__ float sMP[4][64];
    __shared__ float sMax[4];

    stage_tile(sx, b, blockIdx.x * 256 - 3, h, tid);

    const int ch = h * 64 + n;
    const float cw0 = conv_w[ch * 4 + 0];
    const float cw1 = conv_w[ch * 4 + 1];
    const float cw2 = conv_w[ch * 4 + 2];
    const float cw3 = conv_w[ch * 4 + 3];
    const float cb  = conv_b[ch];

    const int s0 = c * 64;
    sS[ty][n] = g_wc[(size_t)(b * S_ + s0 + n) * H_ + h] * w_base[h];
    __syncthreads();

    if (n == 0) {
        float run = 0.f, mn = 3.4e38f, mx = -3.4e38f;
        for (int i = 0; i < 64; i++) {
            run += sS[ty][i];
            sS[ty][i] = run;
            mn = fminf(mn, run);
            sMP[ty][i] = mn;
            mx = fmaxf(mx, run);
        }
        sMax[ty] = mx;
    }
    __syncthreads();
    sE[ty][n]   = __expf(-sS[ty][n]);
    sEMP[ty][n] = __expf(sMP[ty][n]);
    sSDO[ty][n] = __expf(sS[ty][n] - sMax[ty]);
    __syncthreads();

    const int idx = (b * H_ + h) * C_ + c;
    const float ns = g_nstates[idx * N_ + n];
    const float nn = g_nnorm[idx];

    const int r0 = ty * 64;
    float xm3 = __half2float(sx[r0 + 0][n]);
    float xm2 = __half2float(sx[r0 + 1][n]);
    float xm1 = __half2float(sx[r0 + 2][n]);

    float r = 0.f, rn = 0.f;
    __half* yout = g_yh + (size_t)(b * S_ + s0) * DM_ + h * 64 + n;

#pragma unroll 8
    for (int i = 0; i < 64; i++) {
        const float x0 = __half2float(sx[r0 + 3 + i][n]);
        const float xv = cb + cw0 * xm3 + cw1 * xm2 + cw2 * xm1 + cw3 * x0;
        xm3 = xm2; xm2 = xm1; xm1 = x0;
        const float e = sE[ty][i];
        r  = fmaf(e, xv, r);
        rn += e;
        const float emp = sEMP[ty][i];
        const float sdo = sSDO[ty][i];
        const float num = fmaf(sdo, ns, emp * r);
        const float den = fmaf(sdo, nn, emp * rn);
        yout[(size_t)i * DM_] = __float2half_rn(num / den);
    }
}

// ---------------------------------------------------------------------------
// Launch (linear pipeline, 6 kernels)
// ---------------------------------------------------------------------------
extern "C" void kernel_launch(void* const* d_in, const int* in_sizes, int n_in,
                              void* d_out, int out_size)
{
    const float *x = nullptr, *ipw = nullptr, *cw = nullptr,
                *cb = nullptr, *wb = nullptr, *opw = nullptr;
    for (int i = 0; i < n_in; i++) {
        switch (in_sizes[i]) {
            case M_ * DM_:         x   = (const float*)d_in[i]; break;
            case (DM_ + H_) * DM_: ipw = (const float*)d_in[i]; break;
            case DM_ * 4:          cw  = (const float*)d_in[i]; break;
            case DM_:              cb  = (const float*)d_in[i]; break;
            case H_:               wb  = (const float*)d_in[i]; break;
            case DM_ * DM_:        opw = (const float*)d_in[i]; break;
        }
    }

    static bool attr_done = false;
    if (!attr_done) {
        cudaFuncSetAttribute(hgemm_tc<true>,
                             cudaFuncAttributeMaxDynamicSharedMemorySize, GEMM_SMEM);
        cudaFuncSetAttribute(hgemm_tc<false>,
                             cudaFuncAttributeMaxDynamicSharedMemorySize, GEMM_SMEM);
        cudaFuncSetAttribute(wgemm_kernel,
                             cudaFuncAttributeMaxDynamicSharedMemorySize, WGEMM_SMEM);
        attr_done = true;
    }

    // K1b: wgemm (+x fp16 emit, +both weight fp16 conversions)
    wgemm_kernel<<<M_ / 256, 512, WGEMM_SMEM>>>(x, ipw, opw);

    // K1a: xi -> fp16 g_xih
    hgemm_tc<true><<<dim3(DM_ / 256, M_ / 128), 512, GEMM_SMEM>>>(nullptr, DM_);

    // K2: per-chunk stats (smem-staged)
    chunk_stats_kernel<<<dim3(C_ / 4, H_, B_), dim3(64, 4)>>>(cw, cb, wb);

    // K3: cross-chunk scan
    chunk_scan_kernel<<<dim3(H_, B_), 256>>>();

    // K4: combine -> y fp16 (smem-staged)
    combine_kernel<<<dim3(C_ / 4, H_, B_), dim3(64, 4)>>>(cw, cb, wb);

    // K5: out = y @ out_proj_w^T (fp32 out)
    hgemm_tc<false><<<dim3(DM_ / 256, M_ / 128), 512, GEMM_SMEM>>>(
        (float*)d_out, DM_);
}